// round 7
// baseline (speedup 1.0000x reference)
#include <cuda_runtime.h>
#include <stdint.h>

#define NLAYERS 24
#define BATCH   512
#define RDIM    32
#define LQ      256
#define LOUT    257
#define NROWS   (NLAYERS*BATCH*RDIM)      /* 393216 rows */
#define QOUT_ELEMS (NROWS*LOUT)           /* 101,056,512 */
#define QOUT4   (QOUT_ELEMS/4)            /* 25,264,128  */
#define NCOPYB  1184                      /* 148 x 8; occupancy limited by regs */
#define ILP     8
#define FULLMASK 0xffffffffu

// ---------------- scratch (static device globals; no allocation) ----------------
__device__ float2 g_wT [NLAYERS*32*128];   // [l][j][row] -> (w_past, w_h)
__device__ float  g_f1T[NLAYERS*32*128];   // [l][j][k]

__device__ __forceinline__ float sigf(float v) { return 1.0f / (1.0f + __expf(-v)); }

// ---------------- K0: weight transposes ----------------
__global__ void prep_kernel(const float* __restrict__ conv_w,
                            const float* __restrict__ fc1_w) {
    int idx = blockIdx.x * blockDim.x + threadIdx.x;
    if (idx >= NLAYERS * 32 * 128) return;
    {
        int l = idx / 4096, rem = idx & 4095, row = rem / 32, j = rem & 31;
        float2 v = ((const float2*)conv_w)[idx];
        g_wT[(l * 32 + j) * 128 + row] = v;
    }
    {
        int l = idx / 4096, rem = idx & 4095, j = rem >> 7, k = rem & 127;
        g_f1T[idx] = fc1_w[k * 768 + l * 32 + j];
        (void)l;
    }
}

// ---------------- K1: recurrence + head, standalone, unconstrained regs --------
__global__ void __launch_bounds__(256) compute_kernel(
    const float* __restrict__ x,      const float* __restrict__ feat,
    const float* __restrict__ queues,
    const float* __restrict__ fc_h_w, const float* __restrict__ fc_h_b,
    const float* __restrict__ fc_c_w, const float* __restrict__ fc_c_b,
    const float* __restrict__ conv_b,
    const float* __restrict__ fc1_b,  const float* __restrict__ fc2_w,
    const float* __restrict__ fc2_b,
    float* __restrict__ out)
{
    int warp = threadIdx.x >> 5;
    int lane = threadIdx.x & 31;
    int b    = blockIdx.x * 8 + warp;

    float h, c;
    {
        float ha = fc_h_b[lane], ca = fc_c_b[lane];
        #pragma unroll
        for (int i = 0; i < 9; i++) {
            float wh = fc_h_w[lane * 9 + i];
            float wc = fc_c_w[lane * 9 + i];
            float v  = (i == 0) ? x[b] : feat[b * 8 + i - 1];
            ha += wh * v; ca += wc * v;
        }
        h = tanhf(ha); c = tanhf(ca);
    }
    // h BEFORE layer 0 -> t=256 column of layer 0's queue rows
    out[BATCH + (size_t)((0 * BATCH + b) * RDIM + lane) * LOUT + 256] = h;

    float y0 = 0.f, y1 = 0.f, y2 = 0.f, y3 = 0.f;
    float p = __ldg(queues + (size_t)((0 * BATCH + b) * RDIM + lane) * LQ + (LQ - 1));

    #pragma unroll 1
    for (int l = 0; l < NLAYERS; l++) {
        float pn = 0.f;
        if (l < NLAYERS - 1) {
            int dn = 1 << ((l + 1) & 7);
            pn = __ldg(queues + (size_t)(((l + 1) * BATCH + b) * RDIM + lane) * LQ + (LQ - dn));
        }

        float a0 = __ldg(conv_b + l * 128 +  0 + lane);
        float a1 = __ldg(conv_b + l * 128 + 32 + lane);
        float a2 = __ldg(conv_b + l * 128 + 64 + lane);
        float a3 = __ldg(conv_b + l * 128 + 96 + lane);

        const float2* wp = g_wT + l * 32 * 128;
        #pragma unroll 8
        for (int j = 0; j < 32; j++) {
            float pj = __shfl_sync(FULLMASK, p, j);
            float hj = __shfl_sync(FULLMASK, h, j);
            float2 w0 = wp[j * 128 +  0 + lane];
            float2 w1 = wp[j * 128 + 32 + lane];
            float2 w2 = wp[j * 128 + 64 + lane];
            float2 w3 = wp[j * 128 + 96 + lane];
            a0 += w0.x * pj + w0.y * hj;
            a1 += w1.x * pj + w1.y * hj;
            a2 += w2.x * pj + w2.y * hj;
            a3 += w3.x * pj + w3.y * hj;
        }
        c = sigf(a0) * c + tanhf(a1) * sigf(a2);
        h = sigf(a3) * tanhf(c);
        p = pn;

        if (l < NLAYERS - 1)
            out[BATCH + (size_t)(((l + 1) * BATCH + b) * RDIM + lane) * LOUT + 256] = h;

        const float* f1p = g_f1T + l * 32 * 128;
        #pragma unroll 8
        for (int j = 0; j < 32; j++) {
            float hj = __shfl_sync(FULLMASK, h, j);
            y0 += f1p[j * 128 +  0 + lane] * hj;
            y1 += f1p[j * 128 + 32 + lane] * hj;
            y2 += f1p[j * 128 + 64 + lane] * hj;
            y3 += f1p[j * 128 + 96 + lane] * hj;
        }
    }

    float sacc = fmaxf(y0 + fc1_b[ 0 + lane], 0.f) * fc2_w[ 0 + lane]
               + fmaxf(y1 + fc1_b[32 + lane], 0.f) * fc2_w[32 + lane]
               + fmaxf(y2 + fc1_b[64 + lane], 0.f) * fc2_w[64 + lane]
               + fmaxf(y3 + fc1_b[96 + lane], 0.f) * fc2_w[96 + lane];
    #pragma unroll
    for (int off = 16; off > 0; off >>= 1)
        sacc += __shfl_xor_sync(FULLMASK, sacc, off);
    if (lane == 0) out[b] = sacc + fc2_b[0];
}

// ---------------- K2: standalone copy, exactly the R2 loop, free registers -----
__global__ void copy_kernel(const float* __restrict__ queues,
                            float* __restrict__ out)
{
    float4* oq = (float4*)(out + BATCH);
    const unsigned nthr = NCOPYB * 256u;
    unsigned t0 = blockIdx.x * 256u + threadIdx.x;

    for (unsigned base = t0; base < (unsigned)QOUT4; base += nthr * ILP) {
        unsigned idx[ILP];
        float4   v[ILP];
        bool     fast[ILP];
        bool     ok[ILP];
        #pragma unroll
        for (int k = 0; k < ILP; k++) {
            unsigned i4 = base + (unsigned)k * nthr;
            idx[k] = i4;
            ok[k]  = (i4 < (unsigned)QOUT4);
            fast[k] = false;
            if (ok[k]) {
                unsigned e   = i4 * 4u;
                unsigned row = e / 257u;
                unsigned t   = e - row * 257u;
                if (t < 253u) {
                    fast[k] = true;
                    const float* src = queues + (size_t)row * 256u + t;
                    v[k].x = __ldcs(src + 0);
                    v[k].y = __ldcs(src + 1);
                    v[k].z = __ldcs(src + 2);
                    v[k].w = __ldcs(src + 3);
                }
            }
        }
        #pragma unroll
        for (int k = 0; k < ILP; k++) {
            if (!ok[k]) continue;
            if (fast[k]) {
                __stcs(oq + idx[k], v[k]);
            } else {
                // row-wrap / t==256 slow path (t==256 owned by compute kernel)
                unsigned e = idx[k] * 4u;
                #pragma unroll
                for (int j = 0; j < 4; j++) {
                    unsigned ee = e + (unsigned)j;
                    unsigned r2 = ee / 257u;
                    unsigned t2 = ee - r2 * 257u;
                    if (t2 < 256u) {
                        float val = __ldcs(queues + (size_t)r2 * 256u + t2);
                        __stcs(out + BATCH + ee, val);
                    }
                }
            }
        }
    }
}

extern "C" void kernel_launch(void* const* d_in, const int* in_sizes, int n_in,
                              void* d_out, int out_size) {
    const float* x      = (const float*)d_in[0];
    const float* feat   = (const float*)d_in[1];
    const float* queues = (const float*)d_in[2];
    const float* fc_h_w = (const float*)d_in[3];
    const float* fc_h_b = (const float*)d_in[4];
    const float* fc_c_w = (const float*)d_in[5];
    const float* fc_c_b = (const float*)d_in[6];
    const float* conv_w = (const float*)d_in[7];
    const float* conv_b = (const float*)d_in[8];
    const float* fc1_w  = (const float*)d_in[9];
    const float* fc1_b  = (const float*)d_in[10];
    const float* fc2_w  = (const float*)d_in[11];
    const float* fc2_b  = (const float*)d_in[12];
    float* out = (float*)d_out;

    prep_kernel<<<(NLAYERS * 32 * 128 + 255) / 256, 256>>>(conv_w, fc1_w);
    compute_kernel<<<64, 256>>>(x, feat, queues,
                                fc_h_w, fc_h_b, fc_c_w, fc_c_b,
                                conv_b, fc1_b, fc2_w, fc2_b, out);
    copy_kernel<<<NCOPYB, 256>>>(queues, out);
}

// round 8
// speedup vs baseline: 1.8407x; 1.8407x over previous
#include <cuda_runtime.h>
#include <stdint.h>

#define NLAYERS 24
#define BATCH   512
#define RDIM    32
#define LQ      256
#define LOUT    257
#define NROWS   (NLAYERS*BATCH*RDIM)      /* 393216 rows */
#define QOUT_ELEMS (NROWS*LOUT)           /* 101,056,512 */
#define QOUT4   (QOUT_ELEMS/4)            /* 25,264,128  */
#define NCOMPUTE 64                       /* 64 blocks x 8 warps = 512 batches */
#define NCOPYB   1984
#define ILP      8
#define TILE4    (256u*ILP)               /* 2048 float4 = 32KB contiguous per block-iter */
#define FULLMASK 0xffffffffu

// ---------------- scratch (static device globals; no allocation) ----------------
__device__ float2 g_wT [NLAYERS*32*128];   // [l][j][row] -> (w_past, w_h)
__device__ float  g_f1T[NLAYERS*32*128];   // [l][j][k]

__device__ __forceinline__ float sigf(float v) { return 1.0f / (1.0f + __expf(-v)); }

// ---------------- K0: weight transposes for coalesced lane access ----------------
__global__ void prep_kernel(const float* __restrict__ conv_w,
                            const float* __restrict__ fc1_w) {
    int idx = blockIdx.x * blockDim.x + threadIdx.x;
    if (idx >= NLAYERS * 32 * 128) return;
    {
        // conv_w: [l][row(128)][j(32)][2]  (float2 index = (l*128+row)*32 + j)
        int l = idx / 4096, rem = idx & 4095, row = rem / 32, j = rem & 31;
        float2 v = ((const float2*)conv_w)[idx];
        g_wT[(l * 32 + j) * 128 + row] = v;
    }
    {
        // fc1_w: [k(128)][768];  dst [l][j][k], idx == (l*32+j)*128 + k
        int l = idx / 4096, rem = idx & 4095, j = rem >> 7, k = rem & 127;
        g_f1T[idx] = fc1_w[k * 768 + l * 32 + j];
        (void)l;
    }
}

// ---------------- K1: fused recurrence + queue copy (R2 champion + tiled copy) --
__global__ void __launch_bounds__(256, 4) main_kernel(
    const float* __restrict__ x,      const float* __restrict__ feat,
    const float* __restrict__ queues,
    const float* __restrict__ fc_h_w, const float* __restrict__ fc_h_b,
    const float* __restrict__ fc_c_w, const float* __restrict__ fc_c_b,
    const float* __restrict__ conv_b,
    const float* __restrict__ fc1_b,  const float* __restrict__ fc2_w,
    const float* __restrict__ fc2_b,
    float* __restrict__ out)
{
    if (blockIdx.x < NCOMPUTE) {
        // ---- compute path: 1 warp = 1 batch element; lane = R index ----
        int warp = threadIdx.x >> 5;
        int lane = threadIdx.x & 31;
        int b    = blockIdx.x * 8 + warp;

        float h, c;
        {
            float ha = fc_h_b[lane], ca = fc_c_b[lane];
            #pragma unroll
            for (int i = 0; i < 9; i++) {
                float wh = fc_h_w[lane * 9 + i];
                float wc = fc_c_w[lane * 9 + i];
                float v  = (i == 0) ? x[b] : feat[b * 8 + i - 1];
                ha += wh * v; ca += wc * v;
            }
            h = tanhf(ha); c = tanhf(ca);
        }
        // h BEFORE layer 0 -> t=256 column of layer 0's queue rows
        out[BATCH + (size_t)((0 * BATCH + b) * RDIM + lane) * LOUT + 256] = h;

        float y0 = 0.f, y1 = 0.f, y2 = 0.f, y3 = 0.f;

        #pragma unroll 1
        for (int l = 0; l < NLAYERS; l++) {
            int dil = 1 << (l & 7);
            float p = __ldg(queues + (size_t)((l * BATCH + b) * RDIM + lane) * LQ + (LQ - dil));

            float a0 = __ldg(conv_b + l * 128 +  0 + lane);
            float a1 = __ldg(conv_b + l * 128 + 32 + lane);
            float a2 = __ldg(conv_b + l * 128 + 64 + lane);
            float a3 = __ldg(conv_b + l * 128 + 96 + lane);

            const float2* wp = g_wT + l * 32 * 128;
            #pragma unroll 8
            for (int j = 0; j < 32; j++) {
                float pj = __shfl_sync(FULLMASK, p, j);
                float hj = __shfl_sync(FULLMASK, h, j);
                float2 w0 = wp[j * 128 +  0 + lane];
                float2 w1 = wp[j * 128 + 32 + lane];
                float2 w2 = wp[j * 128 + 64 + lane];
                float2 w3 = wp[j * 128 + 96 + lane];
                a0 += w0.x * pj + w0.y * hj;
                a1 += w1.x * pj + w1.y * hj;
                a2 += w2.x * pj + w2.y * hj;
                a3 += w3.x * pj + w3.y * hj;
            }
            c = sigf(a0) * c + tanhf(a1) * sigf(a2);
            h = sigf(a3) * tanhf(c);

            if (l < NLAYERS - 1)
                out[BATCH + (size_t)(((l + 1) * BATCH + b) * RDIM + lane) * LOUT + 256] = h;

            const float* f1p = g_f1T + l * 32 * 128;
            #pragma unroll 8
            for (int j = 0; j < 32; j++) {
                float hj = __shfl_sync(FULLMASK, h, j);
                y0 += f1p[j * 128 +  0 + lane] * hj;
                y1 += f1p[j * 128 + 32 + lane] * hj;
                y2 += f1p[j * 128 + 64 + lane] * hj;
                y3 += f1p[j * 128 + 96 + lane] * hj;
            }
        }

        float sacc = fmaxf(y0 + fc1_b[ 0 + lane], 0.f) * fc2_w[ 0 + lane]
                   + fmaxf(y1 + fc1_b[32 + lane], 0.f) * fc2_w[32 + lane]
                   + fmaxf(y2 + fc1_b[64 + lane], 0.f) * fc2_w[64 + lane]
                   + fmaxf(y3 + fc1_b[96 + lane], 0.f) * fc2_w[96 + lane];
        #pragma unroll
        for (int off = 16; off > 0; off >>= 1)
            sacc += __shfl_xor_sync(FULLMASK, sacc, off);
        if (lane == 0) out[b] = sacc + fc2_b[0];
    } else {
        // ---- copy path: SAME instruction mix as R2, but each block-iteration
        //      covers a CONTIGUOUS 32KB tile (one read stream + one write stream
        //      per block) instead of 8 regions 2MB apart. ----
        float4* oq = (float4*)(out + BATCH);
        const unsigned nblk = NCOPYB;
        unsigned tid  = threadIdx.x;

        for (unsigned tile = (blockIdx.x - NCOMPUTE) * TILE4;
             tile < (unsigned)QOUT4;
             tile += nblk * TILE4) {
            unsigned idx[ILP];
            float4   v[ILP];
            bool     fast[ILP];
            bool     ok[ILP];
            #pragma unroll
            for (int k = 0; k < ILP; k++) {
                unsigned i4 = tile + (unsigned)k * 256u + tid;
                idx[k] = i4;
                ok[k]  = (i4 < (unsigned)QOUT4);
                fast[k] = false;
                if (ok[k]) {
                    unsigned e   = i4 * 4u;
                    unsigned row = e / 257u;
                    unsigned t   = e - row * 257u;
                    if (t < 253u) {
                        fast[k] = true;
                        const float* src = queues + (size_t)row * 256u + t;
                        v[k].x = __ldcs(src + 0);
                        v[k].y = __ldcs(src + 1);
                        v[k].z = __ldcs(src + 2);
                        v[k].w = __ldcs(src + 3);
                    }
                }
            }
            #pragma unroll
            for (int k = 0; k < ILP; k++) {
                if (!ok[k]) continue;
                if (fast[k]) {
                    __stcs(oq + idx[k], v[k]);
                } else {
                    // row-wrap / t==256 slow path (t==256 owned by compute warps)
                    unsigned e = idx[k] * 4u;
                    #pragma unroll
                    for (int j = 0; j < 4; j++) {
                        unsigned ee = e + (unsigned)j;
                        unsigned r2 = ee / 257u;
                        unsigned t2 = ee - r2 * 257u;
                        if (t2 < 256u) {
                            float val = __ldcs(queues + (size_t)r2 * 256u + t2);
                            __stcs(out + BATCH + ee, val);
                        }
                    }
                }
            }
        }
    }
}

extern "C" void kernel_launch(void* const* d_in, const int* in_sizes, int n_in,
                              void* d_out, int out_size) {
    const float* x      = (const float*)d_in[0];
    const float* feat   = (const float*)d_in[1];
    const float* queues = (const float*)d_in[2];
    const float* fc_h_w = (const float*)d_in[3];
    const float* fc_h_b = (const float*)d_in[4];
    const float* fc_c_w = (const float*)d_in[5];
    const float* fc_c_b = (const float*)d_in[6];
    const float* conv_w = (const float*)d_in[7];
    const float* conv_b = (const float*)d_in[8];
    const float* fc1_w  = (const float*)d_in[9];
    const float* fc1_b  = (const float*)d_in[10];
    const float* fc2_w  = (const float*)d_in[11];
    const float* fc2_b  = (const float*)d_in[12];
    float* out = (float*)d_out;

    prep_kernel<<<(NLAYERS * 32 * 128 + 255) / 256, 256>>>(conv_w, fc1_w);
    main_kernel<<<NCOMPUTE + NCOPYB, 256>>>(x, feat, queues,
                                            fc_h_w, fc_h_b, fc_c_w, fc_c_b,
                                            conv_b, fc1_b, fc2_w, fc2_b, out);
}